// round 9
// baseline (speedup 1.0000x reference)
#include <cuda_runtime.h>
#include <cuda_bf16.h>
#include <cstdint>

// Problem constants
constexpr int Bc    = 2;
constexpr int Tc    = 2048;
constexpr int Cc    = 1024;
constexpr int HEAD  = 16;
constexpr int DH    = 64;
constexpr int Wqkv  = 3 * Cc;     // 3072
constexpr int Mrows = Bc * Tc;    // 4096

// Scratch (allocation-free rule: device globals)
__device__ float g_qkv[(size_t)Mrows * Wqkv]; // [B,T,3C], tf32-rounded
__device__ float g_y  [(size_t)Mrows * Cc];   // [B,T,C],  tf32-rounded
__device__ float g_xr [(size_t)Mrows * Cc];   // x tf32-rounded [M][K]
__device__ float g_w1t[(size_t)Wqkv * Cc];    // W_attn^T [N][K], tf32-rounded
__device__ float g_w2t[(size_t)Cc * Cc];      // W_proj^T [N][K], tf32-rounded
__device__ float g_vt [(size_t)Bc * HEAD * DH * Tc]; // V transposed [b][h][d][T]

// ---------------------------------------------------------------------------
// Helpers
// ---------------------------------------------------------------------------
__device__ __forceinline__ uint32_t f2tf32(float x) {
    uint32_t r;
    asm("cvt.rna.tf32.f32 %0, %1;" : "=r"(r) : "f"(x));
    return r;
}

__device__ __forceinline__ uint32_t smem_to_u32(const void* p) {
    uint32_t a;
    asm("{ .reg .u64 t; cvta.to.shared.u64 t, %1; cvt.u32.u64 %0, t; }"
        : "=r"(a) : "l"(p));
    return a;
}

__device__ __forceinline__ void cp_async16(uint32_t dst, const void* src) {
    asm volatile("cp.async.cg.shared.global [%0], [%1], 16;"
                 :: "r"(dst), "l"(src) : "memory");
}
#define CP_COMMIT() asm volatile("cp.async.commit_group;" ::: "memory")
#define CP_WAIT(n)  asm volatile("cp.async.wait_group %0;" :: "n"(n) : "memory")

// ldmatrix x4: four 8x8 b16 tiles == four 8x4 b32 tiles.
__device__ __forceinline__ void ldsm_x4(uint32_t addr, uint32_t* d) {
    asm volatile("ldmatrix.sync.aligned.m8n8.x4.shared.b16 {%0,%1,%2,%3}, [%4];"
                 : "=r"(d[0]), "=r"(d[1]), "=r"(d[2]), "=r"(d[3]) : "r"(addr));
}

// D = A(16x8) * B(8x8) + D, tf32 inputs, fp32 accum.
__device__ __forceinline__ void mma_tf32(float* c, const uint32_t* a, const uint32_t* b) {
    asm volatile(
        "mma.sync.aligned.m16n8k8.row.col.f32.tf32.tf32.f32 "
        "{%0,%1,%2,%3}, {%4,%5,%6,%7}, {%8,%9}, {%0,%1,%2,%3};"
        : "+f"(c[0]), "+f"(c[1]), "+f"(c[2]), "+f"(c[3])
        : "r"(a[0]), "r"(a[1]), "r"(a[2]), "r"(a[3]),
          "r"(b[0]), "r"(b[1]));
}

// ---------------------------------------------------------------------------
// Elementwise tf32 rounding
// ---------------------------------------------------------------------------
__global__ void round_tf32_kernel(const float* __restrict__ in,
                                  float* __restrict__ out, int n4)
{
    int i = blockIdx.x * blockDim.x + threadIdx.x;
    if (i < n4) {
        float4 v = *(const float4*)&in[(size_t)i * 4];
        uint4 u = make_uint4(f2tf32(v.x), f2tf32(v.y), f2tf32(v.z), f2tf32(v.w));
        *(uint4*)&out[(size_t)i * 4] = u;
    }
}

// Transpose + tf32-round: in[K][N] -> out[N][K]
__global__ void transpose_tf32_kernel(const float* __restrict__ in,
                                      float* __restrict__ out, int K, int N)
{
    __shared__ float tile[32][33];
    int k0 = blockIdx.y * 32, n0 = blockIdx.x * 32;
    int tx = threadIdx.x, ty = threadIdx.y;  // 32 x 8
    #pragma unroll
    for (int i = 0; i < 32; i += 8)
        tile[ty + i][tx] = in[(size_t)(k0 + ty + i) * N + n0 + tx];
    __syncthreads();
    #pragma unroll
    for (int i = 0; i < 32; i += 8)
        out[(size_t)(n0 + ty + i) * K + k0 + tx] =
            __uint_as_float(f2tf32(tile[tx][ty + i]));
}

// Transpose V slice of qkv -> g_vt [b][h][d][T]  (values already tf32-rounded)
__global__ void transpose_v_kernel(const float* __restrict__ qkv,
                                   float* __restrict__ vt)
{
    __shared__ float tile[32][33];
    const int bh  = blockIdx.z;
    const int b   = bh / HEAD, h = bh % HEAD;
    const int t0  = blockIdx.x * 32;   // token base
    const int d0  = blockIdx.y * 32;   // d base
    const int tx = threadIdx.x, ty = threadIdx.y;  // 32 x 8
    const float* src = qkv + ((size_t)(b * Tc)) * Wqkv + 2 * Cc + h * DH;
    #pragma unroll
    for (int i = 0; i < 32; i += 8)
        tile[ty + i][tx] = src[(size_t)(t0 + ty + i) * Wqkv + d0 + tx];
    __syncthreads();
    float* dst = vt + ((size_t)bh * DH) * Tc;
    #pragma unroll
    for (int i = 0; i < 32; i += 8)
        dst[(size_t)(d0 + ty + i) * Tc + t0 + tx] = tile[tx][ty + i];
}

// ---------------------------------------------------------------------------
// tf32 GEMM: C[M,N] = A[M,K] @ Bt[N,K]^T + bias[N]
// 128x128x32 tile, 256 threads (8 warps 2x4, warp tile 64x32).
// 3-stage cp.async + ldmatrix. (unchanged from round 7)
// ---------------------------------------------------------------------------
constexpr int G_LD    = 36;
constexpr int G_STAGE = 2 * 128 * G_LD;
constexpr int G_NSTG  = 3;
constexpr int GEMM_SMEM = G_NSTG * G_STAGE * 4;  // 110592 B

__device__ __forceinline__ void gemm_load_stage(
    const float* __restrict__ A, const float* __restrict__ Bt,
    int K, int bm, int bn, int slab, uint32_t s_stage, int tid)
{
    const float* Ag = A + (size_t)bm * K + slab * 32;
    #pragma unroll
    for (int l = 0; l < 4; ++l) {
        int id = tid + l * 256;
        int r = id >> 3, c = (id & 7) * 4;
        cp_async16(s_stage + (uint32_t)(r * G_LD + c) * 4, Ag + (size_t)r * K + c);
    }
    const float* Bg = Bt + (size_t)bn * K + slab * 32;
    uint32_t s_b = s_stage + 128 * G_LD * 4;
    #pragma unroll
    for (int l = 0; l < 4; ++l) {
        int id = tid + l * 256;
        int r = id >> 3, c = (id & 7) * 4;
        cp_async16(s_b + (uint32_t)(r * G_LD + c) * 4, Bg + (size_t)r * K + c);
    }
    CP_COMMIT();
}

__global__ __launch_bounds__(256, 2) void gemm_mma_kernel(
    const float* __restrict__ A, const float* __restrict__ Bt,
    const float* __restrict__ bias, float* __restrict__ Cm,
    int M, int N, int K, int round_out)
{
    extern __shared__ __align__(16) uint32_t gsm[];
    const uint32_t sb = smem_to_u32(gsm);

    const int tid  = threadIdx.x;
    const int w    = tid >> 5;
    const int lane = tid & 31;
    const int g    = lane >> 2;
    const int t    = lane & 3;
    const int wm   = w >> 2;
    const int wn   = w & 3;
    const int bm   = blockIdx.y * 128;
    const int bn   = blockIdx.x * 128;

    const int lrow = lane & 7, lmat = lane >> 3;
    const uint32_t a_frag_off =
        (uint32_t)(((wm * 64 + (lmat & 1) * 8 + lrow) * G_LD + (lmat >> 1) * 4) * 4);
    const uint32_t b_frag_off =
        (uint32_t)(((wn * 32 + (lmat >> 1) * 8 + lrow) * G_LD + (lmat & 1) * 4) * 4);

    float acc[4][4][4];
    #pragma unroll
    for (int mi = 0; mi < 4; ++mi)
        #pragma unroll
        for (int ni = 0; ni < 4; ++ni)
            #pragma unroll
            for (int c = 0; c < 4; ++c) acc[mi][ni][c] = 0.f;

    const int nslab = K / 32;
    gemm_load_stage(A, Bt, K, bm, bn, 0, sb, tid);
    if (nslab > 1) gemm_load_stage(A, Bt, K, bm, bn, 1, sb + G_STAGE * 4, tid);

    int stg = 0;
    for (int i = 0; i < nslab; ++i) {
        if (i + 2 < nslab) {
            int s2 = (stg + 2) % G_NSTG;
            gemm_load_stage(A, Bt, K, bm, bn, i + 2, sb + (uint32_t)s2 * G_STAGE * 4, tid);
            CP_WAIT(2);
        } else if (i + 1 < nslab) {
            CP_WAIT(1);
        } else {
            CP_WAIT(0);
        }
        __syncthreads();

        const uint32_t a_base = sb + (uint32_t)stg * G_STAGE * 4 + a_frag_off;
        const uint32_t b_base = sb + (uint32_t)stg * G_STAGE * 4 + 128 * G_LD * 4 + b_frag_off;

        #pragma unroll
        for (int kc = 0; kc < 4; ++kc) {
            const uint32_t ko = (uint32_t)kc * 32;
            uint32_t af[4][4], bf[2][4];
            #pragma unroll
            for (int mi = 0; mi < 4; ++mi)
                ldsm_x4(a_base + (uint32_t)mi * (16 * G_LD * 4) + ko, af[mi]);
            #pragma unroll
            for (int p = 0; p < 2; ++p)
                ldsm_x4(b_base + (uint32_t)p * (16 * G_LD * 4) + ko, bf[p]);
            #pragma unroll
            for (int mi = 0; mi < 4; ++mi) {
                mma_tf32(acc[mi][0], af[mi], &bf[0][0]);
                mma_tf32(acc[mi][1], af[mi], &bf[0][2]);
                mma_tf32(acc[mi][2], af[mi], &bf[1][0]);
                mma_tf32(acc[mi][3], af[mi], &bf[1][2]);
            }
        }
        __syncthreads();
        stg = (stg + 1) % G_NSTG;
    }

    #pragma unroll
    for (int mi = 0; mi < 4; ++mi) {
        int r0 = bm + wm * 64 + mi * 16 + g;
        #pragma unroll
        for (int ni = 0; ni < 4; ++ni) {
            int col = bn + wn * 32 + ni * 8 + 2 * t;
            float b0 = bias[col], b1 = bias[col + 1];
            float v00 = acc[mi][ni][0] + b0, v01 = acc[mi][ni][1] + b1;
            float v10 = acc[mi][ni][2] + b0, v11 = acc[mi][ni][3] + b1;
            if (round_out) {
                v00 = __uint_as_float(f2tf32(v00));
                v01 = __uint_as_float(f2tf32(v01));
                v10 = __uint_as_float(f2tf32(v10));
                v11 = __uint_as_float(f2tf32(v11));
            }
            *(float2*)&Cm[(size_t)r0 * N + col]       = make_float2(v00, v01);
            *(float2*)&Cm[(size_t)(r0 + 8) * N + col] = make_float2(v10, v11);
        }
    }
}

// ---------------------------------------------------------------------------
// Flash attention (causal), tf32 mma.sync, full-ldmatrix fragments.
// Grid (T/128, H, B), block 256 (8 warps; warp owns 16 q-rows). K tile 64.
// K tiles token-major from g_qkv; V tiles d-major from g_vt.
// ---------------------------------------------------------------------------
constexpr int A_LDK = 68;   // K tile stride (words): [token][d]
constexpr int A_LDV = 68;   // V tile stride (words): [d][token]
constexpr int A_LDP = 68;   // P / Q staging stride
constexpr int OFF_K0 = 0;
constexpr int OFF_K1 = 64 * A_LDK;
constexpr int OFF_V0 = 2 * 64 * A_LDK;
constexpr int OFF_V1 = OFF_V0 + 64 * A_LDV;
constexpr int OFF_P  = OFF_V0 + 2 * 64 * A_LDV;
constexpr int ATTN_SMEM = (OFF_P + 128 * A_LDP) * 4;

__device__ __forceinline__ void attn_load_kv(
    const float* __restrict__ qkv, const float* __restrict__ vt,
    int b, int h, int ktile, uint32_t s_k, uint32_t s_v, int tid)
{
    const float* Kg = qkv + ((size_t)(b * Tc + ktile * 64)) * Wqkv + Cc + h * DH;
    #pragma unroll
    for (int l = 0; l < 4; ++l) {
        int id = tid + l * 256;
        int r = id >> 4, c = (id & 15) * 4;       // 64 token-rows x 16 chunks
        cp_async16(s_k + (uint32_t)(r * A_LDK + c) * 4, Kg + (size_t)r * Wqkv + c);
    }
    const float* Vg = vt + ((size_t)(b * HEAD + h) * DH) * Tc + ktile * 64;
    #pragma unroll
    for (int l = 0; l < 4; ++l) {
        int id = tid + l * 256;
        int r = id >> 4, c = (id & 15) * 4;       // 64 d-rows x 16 token-chunks
        cp_async16(s_v + (uint32_t)(r * A_LDV + c) * 4, Vg + (size_t)r * Tc + c);
    }
    CP_COMMIT();
}

__global__ __launch_bounds__(256) void attn_tc_kernel(
    const float* __restrict__ qkv, const float* __restrict__ vt,
    float* __restrict__ y)
{
    extern __shared__ __align__(16) uint32_t asm_[];
    const uint32_t sb = smem_to_u32(asm_);
    uint32_t* Ps = asm_ + OFF_P;

    const int tid  = threadIdx.x;
    const int w    = tid >> 5;
    const int lane = tid & 31;
    const int g    = lane >> 2;
    const int t    = lane & 3;
    const int rb   = w * 16;

    const int qt = (int)gridDim.x - 1 - (int)blockIdx.x;  // heavy tiles first
    const int h  = blockIdx.y;
    const int b  = blockIdx.z;

    const int lrow = lane & 7, lmat = lane >> 3;
    const uint32_t p_frag_off =
        (uint32_t)(((rb + (lmat & 1) * 8 + lrow) * A_LDP + (lmat >> 1) * 4) * 4);
    const uint32_t k_frag_off =
        (uint32_t)((((lmat >> 1) * 8 + lrow) * A_LDK + (lmat & 1) * 4) * 4);
    const uint32_t v_frag_off =
        (uint32_t)((((lmat >> 1) * 8 + lrow) * A_LDV + (lmat & 1) * 4) * 4);

    // Stage Q tile [128][64] into Ps (group 1)
    {
        const float* Qg = qkv + ((size_t)(b * Tc + qt * 128)) * Wqkv + h * DH;
        #pragma unroll
        for (int l = 0; l < 8; ++l) {
            int id = tid + l * 256;
            int r = id >> 4, c = (id & 15) * 4;
            cp_async16(sb + (uint32_t)(OFF_P + r * A_LDP + c) * 4,
                       Qg + (size_t)r * Wqkv + c);
        }
        CP_COMMIT();
    }
    attn_load_kv(qkv, vt, b, h, 0, sb + OFF_K0 * 4, sb + OFF_V0 * 4, tid);

    CP_WAIT(1);
    __syncthreads();

    uint32_t qa[8][4];
    #pragma unroll
    for (int kc = 0; kc < 8; ++kc) {
        ldsm_x4(sb + OFF_P * 4 + p_frag_off + (uint32_t)kc * 32, qa[kc]);
        #pragma unroll
        for (int j = 0; j < 4; ++j)
            qa[kc][j] = __float_as_uint(__uint_as_float(qa[kc][j]) * 0.125f);
    }

    float o[8][4];
    #pragma unroll
    for (int nf = 0; nf < 8; ++nf)
        #pragma unroll
        for (int c = 0; c < 4; ++c) o[nf][c] = 0.f;
    float m0 = -1e30f, m1 = -1e30f, l0 = 0.f, l1 = 0.f;

    const int nk   = 2 * qt + 2;
    const int qr0g = qt * 128 + rb + g;
    const int qr1g = qr0g + 8;

    for (int kt = 0; kt < nk; ++kt) {
        const int buf = kt & 1;
        if (kt + 1 < nk) {
            attn_load_kv(qkv, vt, b, h, kt + 1,
                         sb + (buf ? OFF_K0 : OFF_K1) * 4,
                         sb + (buf ? OFF_V0 : OFF_V1) * 4, tid);
            CP_WAIT(1);
        } else {
            CP_WAIT(0);
        }
        __syncthreads();

        const uint32_t k_base = sb + (buf ? OFF_K1 : OFF_K0) * 4 + k_frag_off;
        const uint32_t v_base = sb + (buf ? OFF_V1 : OFF_V0) * 4 + v_frag_off;

        // S = Q K^T via ldmatrix B-frags (Ks token-major = n-major)
        float s[8][4];
        #pragma unroll
        for (int ni = 0; ni < 8; ++ni)
            #pragma unroll
            for (int c = 0; c < 4; ++c) s[ni][c] = 0.f;

        #pragma unroll
        for (int kc = 0; kc < 8; ++kc) {
            const uint32_t ko = (uint32_t)kc * 32;
            #pragma unroll
            for (int p = 0; p < 4; ++p) {
                uint32_t kb[4];
                ldsm_x4(k_base + (uint32_t)p * (16 * A_LDK * 4) + ko, kb);
                mma_tf32(s[2 * p    ], qa[kc], &kb[0]);
                mma_tf32(s[2 * p + 1], qa[kc], &kb[2]);
            }
        }

        if (kt >= 2 * qt) {
            int colb = kt * 64;
            #pragma unroll
            for (int ni = 0; ni < 8; ++ni) {
                int c0 = colb + ni * 8 + 2 * t, c1 = c0 + 1;
                if (c0 > qr0g) s[ni][0] = -1e30f;
                if (c1 > qr0g) s[ni][1] = -1e30f;
                if (c0 > qr1g) s[ni][2] = -1e30f;
                if (c1 > qr1g) s[ni][3] = -1e30f;
            }
        }

        float mx0 = -1e30f, mx1 = -1e30f;
        #pragma unroll
        for (int ni = 0; ni < 8; ++ni) {
            mx0 = fmaxf(mx0, fmaxf(s[ni][0], s[ni][1]));
            mx1 = fmaxf(mx1, fmaxf(s[ni][2], s[ni][3]));
        }
        mx0 = fmaxf(mx0, __shfl_xor_sync(0xffffffffu, mx0, 1));
        mx0 = fmaxf(mx0, __shfl_xor_sync(0xffffffffu, mx0, 2));
        mx1 = fmaxf(mx1, __shfl_xor_sync(0xffffffffu, mx1, 1));
        mx1 = fmaxf(mx1, __shfl_xor_sync(0xffffffffu, mx1, 2));

        float mn0 = fmaxf(m0, mx0), mn1 = fmaxf(m1, mx1);
        float a0 = __expf(m0 - mn0), a1 = __expf(m1 - mn1);

        float rs0 = 0.f, rs1 = 0.f;
        #pragma unroll
        for (int ni = 0; ni < 8; ++ni) {
            s[ni][0] = __expf(s[ni][0] - mn0);
            s[ni][1] = __expf(s[ni][1] - mn0);
            s[ni][2] = __expf(s[ni][2] - mn1);
            s[ni][3] = __expf(s[ni][3] - mn1);
            rs0 += s[ni][0] + s[ni][1];
            rs1 += s[ni][2] + s[ni][3];
        }
        rs0 += __shfl_xor_sync(0xffffffffu, rs0, 1);
        rs0 += __shfl_xor_sync(0xffffffffu, rs0, 2);
        rs1 += __shfl_xor_sync(0xffffffffu, rs1, 1);
        rs1 += __shfl_xor_sync(0xffffffffu, rs1, 2);

        l0 = l0 * a0 + rs0;  m0 = mn0;
        l1 = l1 * a1 + rs1;  m1 = mn1;

        #pragma unroll
        for (int nf = 0; nf < 8; ++nf) {
            o[nf][0] *= a0; o[nf][1] *= a0;
            o[nf][2] *= a1; o[nf][3] *= a1;
        }

        // Stage P (warp-private rows), 64-bit stores
        #pragma unroll
        for (int ni = 0; ni < 8; ++ni) {
            int c0 = ni * 8 + 2 * t;
            uint2 v0 = make_uint2(f2tf32(s[ni][0]), f2tf32(s[ni][1]));
            uint2 v1 = make_uint2(f2tf32(s[ni][2]), f2tf32(s[ni][3]));
            *(uint2*)&Ps[(rb + g    ) * A_LDP + c0] = v0;
            *(uint2*)&Ps[(rb + g + 8) * A_LDP + c0] = v1;
        }
        __syncwarp();

        // O += P @ V  — all fragments via ldmatrix now
        #pragma unroll
        for (int kc = 0; kc < 8; ++kc) {
            uint32_t pa[4];
            ldsm_x4(sb + OFF_P * 4 + p_frag_off + (uint32_t)kc * 32, pa);
            const uint32_t ko = (uint32_t)kc * 32;
            #pragma unroll
            for (int p = 0; p < 4; ++p) {
                uint32_t vb[4];
                ldsm_x4(v_base + (uint32_t)p * (16 * A_LDV * 4) + ko, vb);
                mma_tf32(o[2 * p    ], pa, &vb[0]);
                mma_tf32(o[2 * p + 1], pa, &vb[2]);
            }
        }
        __syncwarp();
        __syncthreads();
    }

    float inv0 = 1.f / l0, inv1 = 1.f / l1;
    float* Yg = y + ((size_t)(b * Tc + qt * 128)) * Cc + h * DH;
    #pragma unroll
    for (int nf = 0; nf < 8; ++nf) {
        int c0 = nf * 8 + 2 * t;
        float2 v0 = make_float2(__uint_as_float(f2tf32(o[nf][0] * inv0)),
                                __uint_as_float(f2tf32(o[nf][1] * inv0)));
        float2 v1 = make_float2(__uint_as_float(f2tf32(o[nf][2] * inv1)),
                                __uint_as_float(f2tf32(o[nf][3] * inv1)));
        *(float2*)&Yg[(size_t)(rb + g    ) * Cc + c0] = v0;
        *(float2*)&Yg[(size_t)(rb + g + 8) * Cc + c0] = v1;
    }
}

// ---------------------------------------------------------------------------
// Launch
// ---------------------------------------------------------------------------
extern "C" void kernel_launch(void* const* d_in, const int* in_sizes, int n_in,
                              void* d_out, int out_size)
{
    const float* x      = (const float*)d_in[0];
    const float* W_attn = (const float*)d_in[1];
    const float* b_attn = (const float*)d_in[2];
    const float* W_proj = (const float*)d_in[3];
    const float* b_proj = (const float*)d_in[4];
    float* out = (float*)d_out;

    float *qkv_p, *y_p, *xr_p, *w1t_p, *w2t_p, *vt_p;
    cudaGetSymbolAddress((void**)&qkv_p, g_qkv);
    cudaGetSymbolAddress((void**)&y_p,   g_y);
    cudaGetSymbolAddress((void**)&xr_p,  g_xr);
    cudaGetSymbolAddress((void**)&w1t_p, g_w1t);
    cudaGetSymbolAddress((void**)&w2t_p, g_w2t);
    cudaGetSymbolAddress((void**)&vt_p,  g_vt);

    cudaFuncSetAttribute(gemm_mma_kernel,
                         cudaFuncAttributeMaxDynamicSharedMemorySize, GEMM_SMEM);
    cudaFuncSetAttribute(attn_tc_kernel,
                         cudaFuncAttributeMaxDynamicSharedMemorySize, ATTN_SMEM);

    // 0) Pre-round x; transpose+round weights to [N][K]
    {
        int n4 = (Mrows * Cc) / 4;
        round_tf32_kernel<<<(n4 + 255) / 256, 256>>>(x, xr_p, n4);
        transpose_tf32_kernel<<<dim3(Wqkv / 32, Cc / 32), dim3(32, 8)>>>(W_attn, w1t_p, Cc, Wqkv);
        transpose_tf32_kernel<<<dim3(Cc / 32,  Cc / 32), dim3(32, 8)>>>(W_proj, w2t_p, Cc, Cc);
    }

    // 1) QKV = x @ W_attn + b_attn   [4096, 3072], outputs tf32-rounded
    gemm_mma_kernel<<<dim3(Wqkv / 128, Mrows / 128), 256, GEMM_SMEM>>>(
        xr_p, w1t_p, b_attn, qkv_p, Mrows, Wqkv, Cc, 1);

    // 1b) Transpose V slice -> g_vt [b][h][d][T]
    transpose_v_kernel<<<dim3(Tc / 32, DH / 32, Bc * HEAD), dim3(32, 8)>>>(qkv_p, vt_p);

    // 2) causal flash attention -> g_y (tf32-rounded)
    attn_tc_kernel<<<dim3(Tc / 128, HEAD, Bc), 256, ATTN_SMEM>>>(qkv_p, vt_p, y_p);

    // 3) out = y @ W_proj + b_proj   [4096, 1024], full fp32 out
    gemm_mma_kernel<<<dim3(Cc / 128, Mrows / 128), 256, GEMM_SMEM>>>(
        y_p, w2t_p, b_proj, out, Mrows, Cc, Cc, 0);
}

// round 10
// speedup vs baseline: 1.0342x; 1.0342x over previous
#include <cuda_runtime.h>
#include <cuda_bf16.h>
#include <cstdint>

// Problem constants
constexpr int Bc    = 2;
constexpr int Tc    = 2048;
constexpr int Cc    = 1024;
constexpr int HEAD  = 16;
constexpr int DH    = 64;
constexpr int Wqkv  = 3 * Cc;     // 3072
constexpr int Mrows = Bc * Tc;    // 4096

// Scratch (allocation-free rule: device globals)
__device__ float g_qkv[(size_t)Mrows * Wqkv]; // [B,T,3C], tf32-rounded
__device__ float g_y  [(size_t)Mrows * Cc];   // [B,T,C],  tf32-rounded
__device__ float g_xr [(size_t)Mrows * Cc];   // x tf32-rounded [M][K]
__device__ float g_w1t[(size_t)Wqkv * Cc];    // W_attn^T [N][K], tf32-rounded
__device__ float g_w2t[(size_t)Cc * Cc];      // W_proj^T [N][K], tf32-rounded

// ---------------------------------------------------------------------------
// Helpers
// ---------------------------------------------------------------------------
__device__ __forceinline__ uint32_t f2tf32(float x) {
    uint32_t r;
    asm("cvt.rna.tf32.f32 %0, %1;" : "=r"(r) : "f"(x));
    return r;
}

__device__ __forceinline__ uint32_t smem_to_u32(const void* p) {
    uint32_t a;
    asm("{ .reg .u64 t; cvta.to.shared.u64 t, %1; cvt.u32.u64 %0, t; }"
        : "=r"(a) : "l"(p));
    return a;
}

__device__ __forceinline__ void cp_async16(uint32_t dst, const void* src) {
    asm volatile("cp.async.cg.shared.global [%0], [%1], 16;"
                 :: "r"(dst), "l"(src) : "memory");
}
#define CP_COMMIT() asm volatile("cp.async.commit_group;" ::: "memory")
#define CP_WAIT(n)  asm volatile("cp.async.wait_group %0;" :: "n"(n) : "memory")

// ldmatrix x4: four 8x8 b16 tiles == four 8x4 b32 tiles.
__device__ __forceinline__ void ldsm_x4(uint32_t addr, uint32_t* d) {
    asm volatile("ldmatrix.sync.aligned.m8n8.x4.shared.b16 {%0,%1,%2,%3}, [%4];"
                 : "=r"(d[0]), "=r"(d[1]), "=r"(d[2]), "=r"(d[3]) : "r"(addr));
}

// D = A(16x8) * B(8x8) + D, tf32 inputs, fp32 accum.
__device__ __forceinline__ void mma_tf32(float* c, const uint32_t* a, const uint32_t* b) {
    asm volatile(
        "mma.sync.aligned.m16n8k8.row.col.f32.tf32.tf32.f32 "
        "{%0,%1,%2,%3}, {%4,%5,%6,%7}, {%8,%9}, {%0,%1,%2,%3};"
        : "+f"(c[0]), "+f"(c[1]), "+f"(c[2]), "+f"(c[3])
        : "r"(a[0]), "r"(a[1]), "r"(a[2]), "r"(a[3]),
          "r"(b[0]), "r"(b[1]));
}

// ---------------------------------------------------------------------------
// Elementwise tf32 rounding
// ---------------------------------------------------------------------------
__global__ void round_tf32_kernel(const float* __restrict__ in,
                                  float* __restrict__ out, int n4)
{
    int i = blockIdx.x * blockDim.x + threadIdx.x;
    if (i < n4) {
        float4 v = *(const float4*)&in[(size_t)i * 4];
        uint4 u = make_uint4(f2tf32(v.x), f2tf32(v.y), f2tf32(v.z), f2tf32(v.w));
        *(uint4*)&out[(size_t)i * 4] = u;
    }
}

// Transpose + tf32-round: in[K][N] -> out[N][K]
__global__ void transpose_tf32_kernel(const float* __restrict__ in,
                                      float* __restrict__ out, int K, int N)
{
    __shared__ float tile[32][33];
    int k0 = blockIdx.y * 32, n0 = blockIdx.x * 32;
    int tx = threadIdx.x, ty = threadIdx.y;  // 32 x 8
    #pragma unroll
    for (int i = 0; i < 32; i += 8)
        tile[ty + i][tx] = in[(size_t)(k0 + ty + i) * N + n0 + tx];
    __syncthreads();
    #pragma unroll
    for (int i = 0; i < 32; i += 8)
        out[(size_t)(n0 + ty + i) * K + k0 + tx] =
            __uint_as_float(f2tf32(tile[tx][ty + i]));
}

// ---------------------------------------------------------------------------
// tf32 GEMM: C[M,N] = A[M,K] @ Bt[N,K]^T + bias[N]
// 128x128x32 tile, 256 threads (8 warps 2x4, warp tile 64x32).
// 3-stage cp.async pipeline, ONE __syncthreads per k-slab.
// ---------------------------------------------------------------------------
constexpr int G_LD    = 36;
constexpr int G_STAGE = 2 * 128 * G_LD;
constexpr int G_NSTG  = 3;
constexpr int GEMM_SMEM = G_NSTG * G_STAGE * 4;  // 110592 B

__device__ __forceinline__ void gemm_load_stage(
    const float* __restrict__ A, const float* __restrict__ Bt,
    int K, int bm, int bn, int slab, uint32_t s_stage, int tid)
{
    const float* Ag = A + (size_t)bm * K + slab * 32;
    #pragma unroll
    for (int l = 0; l < 4; ++l) {
        int id = tid + l * 256;
        int r = id >> 3, c = (id & 7) * 4;
        cp_async16(s_stage + (uint32_t)(r * G_LD + c) * 4, Ag + (size_t)r * K + c);
    }
    const float* Bg = Bt + (size_t)bn * K + slab * 32;
    uint32_t s_b = s_stage + 128 * G_LD * 4;
    #pragma unroll
    for (int l = 0; l < 4; ++l) {
        int id = tid + l * 256;
        int r = id >> 3, c = (id & 7) * 4;
        cp_async16(s_b + (uint32_t)(r * G_LD + c) * 4, Bg + (size_t)r * K + c);
    }
    CP_COMMIT();
}

__global__ __launch_bounds__(256, 2) void gemm_mma_kernel(
    const float* __restrict__ A, const float* __restrict__ Bt,
    const float* __restrict__ bias, float* __restrict__ Cm,
    int M, int N, int K, int round_out)
{
    extern __shared__ __align__(16) uint32_t gsm[];
    const uint32_t sb = smem_to_u32(gsm);

    const int tid  = threadIdx.x;
    const int w    = tid >> 5;
    const int lane = tid & 31;
    const int g    = lane >> 2;
    const int t    = lane & 3;
    const int wm   = w >> 2;
    const int wn   = w & 3;
    const int bm   = blockIdx.y * 128;
    const int bn   = blockIdx.x * 128;

    const int lrow = lane & 7, lmat = lane >> 3;
    const uint32_t a_frag_off =
        (uint32_t)(((wm * 64 + (lmat & 1) * 8 + lrow) * G_LD + (lmat >> 1) * 4) * 4);
    const uint32_t b_frag_off =
        (uint32_t)(((wn * 32 + (lmat >> 1) * 8 + lrow) * G_LD + (lmat & 1) * 4) * 4);

    float acc[4][4][4];
    #pragma unroll
    for (int mi = 0; mi < 4; ++mi)
        #pragma unroll
        for (int ni = 0; ni < 4; ++ni)
            #pragma unroll
            for (int c = 0; c < 4; ++c) acc[mi][ni][c] = 0.f;

    const int nslab = K / 32;
    gemm_load_stage(A, Bt, K, bm, bn, 0, sb, tid);
    if (nslab > 1) gemm_load_stage(A, Bt, K, bm, bn, 1, sb + G_STAGE * 4, tid);

    int stg = 0;
    for (int i = 0; i < nslab; ++i) {
        // Wait for stage i's data (allow stage i+1's group to stay in flight),
        // then one barrier: all warps are past iteration i-1 (which last read
        // stage (i+2)%3), so refilling it below is race-free.
        if (i + 1 < nslab) { CP_WAIT(1); } else { CP_WAIT(0); }
        __syncthreads();
        if (i + 2 < nslab) {
            int s2 = (stg + 2) % G_NSTG;
            gemm_load_stage(A, Bt, K, bm, bn, i + 2, sb + (uint32_t)s2 * G_STAGE * 4, tid);
        }

        const uint32_t a_base = sb + (uint32_t)stg * G_STAGE * 4 + a_frag_off;
        const uint32_t b_base = sb + (uint32_t)stg * G_STAGE * 4 + 128 * G_LD * 4 + b_frag_off;

        #pragma unroll
        for (int kc = 0; kc < 4; ++kc) {
            const uint32_t ko = (uint32_t)kc * 32;
            uint32_t af[4][4], bf[2][4];
            #pragma unroll
            for (int mi = 0; mi < 4; ++mi)
                ldsm_x4(a_base + (uint32_t)mi * (16 * G_LD * 4) + ko, af[mi]);
            #pragma unroll
            for (int p = 0; p < 2; ++p)
                ldsm_x4(b_base + (uint32_t)p * (16 * G_LD * 4) + ko, bf[p]);
            #pragma unroll
            for (int mi = 0; mi < 4; ++mi) {
                mma_tf32(acc[mi][0], af[mi], &bf[0][0]);
                mma_tf32(acc[mi][1], af[mi], &bf[0][2]);
                mma_tf32(acc[mi][2], af[mi], &bf[1][0]);
                mma_tf32(acc[mi][3], af[mi], &bf[1][2]);
            }
        }
        stg = (stg + 1) % G_NSTG;
    }

    #pragma unroll
    for (int mi = 0; mi < 4; ++mi) {
        int r0 = bm + wm * 64 + mi * 16 + g;
        #pragma unroll
        for (int ni = 0; ni < 4; ++ni) {
            int col = bn + wn * 32 + ni * 8 + 2 * t;
            float b0 = bias[col], b1 = bias[col + 1];
            float v00 = acc[mi][ni][0] + b0, v01 = acc[mi][ni][1] + b1;
            float v10 = acc[mi][ni][2] + b0, v11 = acc[mi][ni][3] + b1;
            if (round_out) {
                v00 = __uint_as_float(f2tf32(v00));
                v01 = __uint_as_float(f2tf32(v01));
                v10 = __uint_as_float(f2tf32(v10));
                v11 = __uint_as_float(f2tf32(v11));
            }
            *(float2*)&Cm[(size_t)r0 * N + col]       = make_float2(v00, v01);
            *(float2*)&Cm[(size_t)(r0 + 8) * N + col] = make_float2(v10, v11);
        }
    }
}

// ---------------------------------------------------------------------------
// Flash attention (causal), tf32 mma.sync + ldmatrix Q/K/P, scalar V frags.
// Grid (T/128, H, B), block 256 (8 warps). K tile 64.
// ONE __syncthreads per k-tile (loads issued after the barrier).
// ---------------------------------------------------------------------------
constexpr int A_LDK = 68;
constexpr int A_LDV = 72;
constexpr int A_LDP = 68;
constexpr int OFF_K0 = 0;
constexpr int OFF_K1 = 64 * A_LDK;
constexpr int OFF_V0 = 2 * 64 * A_LDK;
constexpr int OFF_V1 = OFF_V0 + 64 * A_LDV;
constexpr int OFF_P  = OFF_V0 + 2 * 64 * A_LDV;
constexpr int ATTN_SMEM = (OFF_P + 128 * A_LDP) * 4;   // 106496 B

__device__ __forceinline__ void attn_load_kv(
    const float* __restrict__ qkv, int b, int h, int ktile,
    uint32_t s_k, uint32_t s_v, int tid)
{
    const float* Kg = qkv + ((size_t)(b * Tc + ktile * 64)) * Wqkv + Cc + h * DH;
    const float* Vg = Kg + Cc;
    #pragma unroll
    for (int l = 0; l < 4; ++l) {
        int id = tid + l * 256;
        int r = id >> 4, c = (id & 15) * 4;
        cp_async16(s_k + (uint32_t)(r * A_LDK + c) * 4, Kg + (size_t)r * Wqkv + c);
    }
    #pragma unroll
    for (int l = 0; l < 4; ++l) {
        int id = tid + l * 256;
        int r = id >> 4, c = (id & 15) * 4;
        cp_async16(s_v + (uint32_t)(r * A_LDV + c) * 4, Vg + (size_t)r * Wqkv + c);
    }
    CP_COMMIT();
}

__global__ __launch_bounds__(256) void attn_tc_kernel(
    const float* __restrict__ qkv, float* __restrict__ y)
{
    extern __shared__ __align__(16) uint32_t asm_[];
    const uint32_t sb = smem_to_u32(asm_);
    uint32_t* Ps = asm_ + OFF_P;

    const int tid  = threadIdx.x;
    const int w    = tid >> 5;
    const int lane = tid & 31;
    const int g    = lane >> 2;
    const int t    = lane & 3;
    const int rb   = w * 16;

    const int qt = (int)gridDim.x - 1 - (int)blockIdx.x;  // heavy tiles first
    const int h  = blockIdx.y;
    const int b  = blockIdx.z;

    const int lrow = lane & 7, lmat = lane >> 3;
    const uint32_t p_frag_off =
        (uint32_t)(((rb + (lmat & 1) * 8 + lrow) * A_LDP + (lmat >> 1) * 4) * 4);
    const uint32_t k_frag_off =
        (uint32_t)((((lmat >> 1) * 8 + lrow) * A_LDK + (lmat & 1) * 4) * 4);

    // Stage Q tile [128][64] into Ps (group 1), prefetch K/V tile 0 (group 2)
    {
        const float* Qg = qkv + ((size_t)(b * Tc + qt * 128)) * Wqkv + h * DH;
        #pragma unroll
        for (int l = 0; l < 8; ++l) {
            int id = tid + l * 256;
            int r = id >> 4, c = (id & 15) * 4;
            cp_async16(sb + (uint32_t)(OFF_P + r * A_LDP + c) * 4,
                       Qg + (size_t)r * Wqkv + c);
        }
        CP_COMMIT();
    }
    attn_load_kv(qkv, b, h, 0, sb + OFF_K0 * 4, sb + OFF_V0 * 4, tid);

    CP_WAIT(1);
    __syncthreads();

    uint32_t qa[8][4];
    #pragma unroll
    for (int kc = 0; kc < 8; ++kc) {
        ldsm_x4(sb + OFF_P * 4 + p_frag_off + (uint32_t)kc * 32, qa[kc]);
        #pragma unroll
        for (int j = 0; j < 4; ++j)
            qa[kc][j] = __float_as_uint(__uint_as_float(qa[kc][j]) * 0.125f);
    }

    float o[8][4];
    #pragma unroll
    for (int nf = 0; nf < 8; ++nf)
        #pragma unroll
        for (int c = 0; c < 4; ++c) o[nf][c] = 0.f;
    float m0 = -1e30f, m1 = -1e30f, l0 = 0.f, l1 = 0.f;

    const int nk   = 2 * qt + 2;
    const int qr0g = qt * 128 + rb + g;
    const int qr1g = qr0g + 8;

    for (int kt = 0; kt < nk; ++kt) {
        const int buf = kt & 1;
        // One barrier per k-tile: data for kt is in, all warps past kt-1
        // (which last read buf^1), so issuing kt+1's loads into buf^1 is safe.
        CP_WAIT(0);
        __syncthreads();
        if (kt + 1 < nk)
            attn_load_kv(qkv, b, h, kt + 1,
                         sb + (buf ? OFF_K0 : OFF_K1) * 4,
                         sb + (buf ? OFF_V0 : OFF_V1) * 4, tid);

        const uint32_t k_base = sb + (buf ? OFF_K1 : OFF_K0) * 4 + k_frag_off;
        const uint32_t* Vs = asm_ + (buf ? OFF_V1 : OFF_V0);

        // S = Q K^T via ldmatrix B-frags (Ks token-major = n-major)
        float s[8][4];
        #pragma unroll
        for (int ni = 0; ni < 8; ++ni)
            #pragma unroll
            for (int c = 0; c < 4; ++c) s[ni][c] = 0.f;

        #pragma unroll
        for (int kc = 0; kc < 8; ++kc) {
            const uint32_t ko = (uint32_t)kc * 32;
            #pragma unroll
            for (int p = 0; p < 4; ++p) {
                uint32_t kb[4];
                ldsm_x4(k_base + (uint32_t)p * (16 * A_LDK * 4) + ko, kb);
                mma_tf32(s[2 * p    ], qa[kc], &kb[0]);
                mma_tf32(s[2 * p + 1], qa[kc], &kb[2]);
            }
        }

        if (kt >= 2 * qt) {
            int colb = kt * 64;
            #pragma unroll
            for (int ni = 0; ni < 8; ++ni) {
                int c0 = colb + ni * 8 + 2 * t, c1 = c0 + 1;
                if (c0 > qr0g) s[ni][0] = -1e30f;
                if (c1 > qr0g) s[ni][1] = -1e30f;
                if (c0 > qr1g) s[ni][2] = -1e30f;
                if (c1 > qr1g) s[ni][3] = -1e30f;
            }
        }

        float mx0 = -1e30f, mx1 = -1e30f;
        #pragma unroll
        for (int ni = 0; ni < 8; ++ni) {
            mx0 = fmaxf(mx0, fmaxf(s[ni][0], s[ni][1]));
            mx1 = fmaxf(mx1, fmaxf(s[ni][2], s[ni][3]));
        }
        mx0 = fmaxf(mx0, __shfl_xor_sync(0xffffffffu, mx0, 1));
        mx0 = fmaxf(mx0, __shfl_xor_sync(0xffffffffu, mx0, 2));
        mx1 = fmaxf(mx1, __shfl_xor_sync(0xffffffffu, mx1, 1));
        mx1 = fmaxf(mx1, __shfl_xor_sync(0xffffffffu, mx1, 2));

        float mn0 = fmaxf(m0, mx0), mn1 = fmaxf(m1, mx1);
        float a0 = __expf(m0 - mn0), a1 = __expf(m1 - mn1);

        float rs0 = 0.f, rs1 = 0.f;
        #pragma unroll
        for (int ni = 0; ni < 8; ++ni) {
            s[ni][0] = __expf(s[ni][0] - mn0);
            s[ni][1] = __expf(s[ni][1] - mn0);
            s[ni][2] = __expf(s[ni][2] - mn1);
            s[ni][3] = __expf(s[ni][3] - mn1);
            rs0 += s[ni][0] + s[ni][1];
            rs1 += s[ni][2] + s[ni][3];
        }
        rs0 += __shfl_xor_sync(0xffffffffu, rs0, 1);
        rs0 += __shfl_xor_sync(0xffffffffu, rs0, 2);
        rs1 += __shfl_xor_sync(0xffffffffu, rs1, 1);
        rs1 += __shfl_xor_sync(0xffffffffu, rs1, 2);

        l0 = l0 * a0 + rs0;  m0 = mn0;
        l1 = l1 * a1 + rs1;  m1 = mn1;

        #pragma unroll
        for (int nf = 0; nf < 8; ++nf) {
            o[nf][0] *= a0; o[nf][1] *= a0;
            o[nf][2] *= a1; o[nf][3] *= a1;
        }

        // Stage P (warp-private rows), 64-bit stores
        #pragma unroll
        for (int ni = 0; ni < 8; ++ni) {
            int c0 = ni * 8 + 2 * t;
            uint2 v0 = make_uint2(f2tf32(s[ni][0]), f2tf32(s[ni][1]));
            uint2 v1 = make_uint2(f2tf32(s[ni][2]), f2tf32(s[ni][3]));
            *(uint2*)&Ps[(rb + g    ) * A_LDP + c0] = v0;
            *(uint2*)&Ps[(rb + g + 8) * A_LDP + c0] = v1;
        }
        __syncwarp();

        // O += P @ V  (pa via ldmatrix; V frags scalar, conflict-free)
        #pragma unroll
        for (int kc = 0; kc < 8; ++kc) {
            uint32_t pa[4];
            ldsm_x4(sb + OFF_P * 4 + p_frag_off + (uint32_t)kc * 32, pa);
            #pragma unroll
            for (int nf = 0; nf < 8; ++nf) {
                uint32_t bf[2];
                bf[0] = Vs[(kc * 8 + t    ) * A_LDV + nf * 8 + g];
                bf[1] = Vs[(kc * 8 + t + 4) * A_LDV + nf * 8 + g];
                mma_tf32(o[nf], pa, bf);
            }
        }
    }

    float inv0 = 1.f / l0, inv1 = 1.f / l1;
    float* Yg = y + ((size_t)(b * Tc + qt * 128)) * Cc + h * DH;
    #pragma unroll
    for (int nf = 0; nf < 8; ++nf) {
        int c0 = nf * 8 + 2 * t;
        float2 v0 = make_float2(__uint_as_float(f2tf32(o[nf][0] * inv0)),
                                __uint_as_float(f2tf32(o[nf][1] * inv0)));
        float2 v1 = make_float2(__uint_as_float(f2tf32(o[nf][2] * inv1)),
                                __uint_as_float(f2tf32(o[nf][3] * inv1)));
        *(float2*)&Yg[(size_t)(rb + g    ) * Cc + c0] = v0;
        *(float2*)&Yg[(size_t)(rb + g + 8) * Cc + c0] = v1;
    }
}

// ---------------------------------------------------------------------------
// Launch
// ---------------------------------------------------------------------------
extern "C" void kernel_launch(void* const* d_in, const int* in_sizes, int n_in,
                              void* d_out, int out_size)
{
    const float* x      = (const float*)d_in[0];
    const float* W_attn = (const float*)d_in[1];
    const float* b_attn = (const float*)d_in[2];
    const float* W_proj = (const float*)d_in[3];
    const float* b_proj = (const float*)d_in[4];
    float* out = (float*)d_out;

    float *qkv_p, *y_p, *xr_p, *w1t_p, *w2t_p;
    cudaGetSymbolAddress((void**)&qkv_p, g_qkv);
    cudaGetSymbolAddress((void**)&y_p,   g_y);
    cudaGetSymbolAddress((void**)&xr_p,  g_xr);
    cudaGetSymbolAddress((void**)&w1t_p, g_w1t);
    cudaGetSymbolAddress((void**)&w2t_p, g_w2t);

    cudaFuncSetAttribute(gemm_mma_kernel,
                         cudaFuncAttributeMaxDynamicSharedMemorySize, GEMM_SMEM);
    cudaFuncSetAttribute(attn_tc_kernel,
                         cudaFuncAttributeMaxDynamicSharedMemorySize, ATTN_SMEM);

    // 0) Pre-round x; transpose+round weights to [N][K]
    {
        int n4 = (Mrows * Cc) / 4;
        round_tf32_kernel<<<(n4 + 255) / 256, 256>>>(x, xr_p, n4);
        transpose_tf32_kernel<<<dim3(Wqkv / 32, Cc / 32), dim3(32, 8)>>>(W_attn, w1t_p, Cc, Wqkv);
        transpose_tf32_kernel<<<dim3(Cc / 32,  Cc / 32), dim3(32, 8)>>>(W_proj, w2t_p, Cc, Cc);
    }

    // 1) QKV = x @ W_attn + b_attn   [4096, 3072], outputs tf32-rounded
    gemm_mma_kernel<<<dim3(Wqkv / 128, Mrows / 128), 256, GEMM_SMEM>>>(
        xr_p, w1t_p, b_attn, qkv_p, Mrows, Wqkv, Cc, 1);

    // 2) causal flash attention -> g_y (tf32-rounded)
    attn_tc_kernel<<<dim3(Tc / 128, HEAD, Bc), 256, ATTN_SMEM>>>(qkv_p, y_p);

    // 3) out = y @ W_proj + b_proj   [4096, 1024], full fp32 out
    gemm_mma_kernel<<<dim3(Cc / 128, Mrows / 128), 256, GEMM_SMEM>>>(
        y_p, w2t_p, b_proj, out, Mrows, Cc, Cc, 0);
}